// round 10
// baseline (speedup 1.0000x reference)
#include <cuda_runtime.h>
#include <cuda_bf16.h>
#include <stdint.h>

#define NT16   8704          // 139264 / 16 points
#define TEQ    8192
#define TIB    8448
#define NU     0.0031830988618379067154f

// W1..W3 bf16 fragments, h and l splits separate: [l][ks][nt][lane] -> uint2{b0,b1}
__device__ uint2 g_wfH[12288];
__device__ uint2 g_wfL[12288];

__device__ __forceinline__ uint32_t pkbf(float lo, float hi) {
    uint32_t r; asm("cvt.rn.bf16x2.f32 %0, %1, %2;" : "=r"(r) : "f"(hi), "f"(lo)); return r;
}
__device__ __forceinline__ void split2(float v0, float v1, uint32_t& h, uint32_t& l) {
    h = pkbf(v0, v1);
    float h0 = __uint_as_float(h << 16);
    float h1 = __uint_as_float(h & 0xffff0000u);
    l = pkbf(v0 - h0, v1 - h1);
}
__device__ __forceinline__ float tanhf_fast(float z) {
    float e = __expf(2.0f * z);
    return __fdividef(e - 1.0f, e + 1.0f);
}
__device__ __forceinline__ void mma16816(float* c, const uint32_t* a, uint32_t b0, uint32_t b1) {
    asm volatile(
        "mma.sync.aligned.m16n8k16.row.col.f32.bf16.bf16.f32 "
        "{%0,%1,%2,%3}, {%4,%5,%6,%7}, {%8,%9}, {%0,%1,%2,%3};"
        : "+f"(c[0]), "+f"(c[1]), "+f"(c[2]), "+f"(c[3])
        : "r"(a[0]), "r"(a[1]), "r"(a[2]), "r"(a[3]), "r"(b0), "r"(b1));
}
__device__ __forceinline__ void gbar(int id) {
    asm volatile("bar.sync %0, 128;" :: "r"(id) : "memory");
}

__global__ void prep_kernel(const float* __restrict__ W1,
                            const float* __restrict__ W2,
                            const float* __restrict__ W3)
{
    const int gt   = blockIdx.x * blockDim.x + threadIdx.x;   // 0..12287
    const int lane = gt & 31;
    const int wi   = gt >> 5;
    const int nt   = wi & 15;
    const int ks   = (wi >> 4) & 7;
    const int l    = wi >> 7;
    const float* W = (l == 0) ? W1 : (l == 1) ? W2 : W3;
    const int j  = nt * 8 + (lane >> 2);
    const int k0 = ks * 16 + 2 * (lane & 3);
    uint32_t h0, l0, h1, l1;
    split2(W[(k0    ) * 128 + j], W[(k0 + 1) * 128 + j], h0, l0);
    split2(W[(k0 + 8) * 128 + j], W[(k0 + 9) * 128 + j], h1, l1);
    g_wfH[wi * 32 + lane] = make_uint2(h0, h1);
    g_wfL[wi * 32 + lane] = make_uint2(l0, l1);
}

// smem: sWfH 98304 | sWfL 98304 | exA 2 groups x 16 x 130 f | exX same
#define EXA_OFF  196608
#define EXX_OFF  213248
#define SMEM_BYTES 229888

extern __shared__ char smem_raw[];

__global__ __launch_bounds__(256, 1)
void pinn_mma(const float* __restrict__ tx_eq, const float* __restrict__ tx_init,
              const float* __restrict__ tx_bnd,
              const float* __restrict__ W0, const float* __restrict__ b0,
              const float* __restrict__ b1, const float* __restrict__ b2,
              const float* __restrict__ b3,
              const float* __restrict__ W4, const float* __restrict__ b4,
              float* __restrict__ out)
{
    uint2* sWfH = (uint2*)smem_raw;
    uint2* sWfL = (uint2*)(smem_raw + 98304);

    const int tid  = threadIdx.x;
    const int lane = tid & 31;
    const int w    = tid >> 5;
    const int g    = w >> 2;         // tile group 0/1 (w0-3 vs w4-7)
    const int s    = w & 3;          // state: 0=a 1=t 2=x 3=xx  (also SMSP id)
    const int bid  = g + 1;          // named barrier id
    const int q    = lane & 3;
    const int ra   = lane >> 2;      // 0..7
    const int rb   = ra + 8;

    float* exA = (float*)(smem_raw + EXA_OFF) + g * 2080;   // 16*130
    float* exX = (float*)(smem_raw + EXX_OFF) + g * 2080;

    {
        uint2* d = (uint2*)smem_raw;
        for (int i = tid; i < 12288; i += 256) { d[i] = g_wfH[i]; d[12288 + i] = g_wfL[i]; }
    }
    const float b4v = __ldg(b4);
    __syncthreads();

    for (int tile = blockIdx.x * 2 + g; tile < NT16; tile += gridDim.x * 2) {
        const float2* src;
        if (tile < TEQ)      src = (const float2*)tx_eq  + tile * 16;
        else if (tile < TIB) src = (const float2*)tx_init + (tile - TEQ) * 16;
        else                 src = (const float2*)tx_bnd  + (tile - TIB) * 16;

        const float2 Pa = __ldg(src + ra);
        const float2 Pb = __ldg(src + rb);

        float c[16][4];

        // ---- layer 0: every warp computes its state's seeds (C layout) ----
        #pragma unroll
        for (int nt = 0; nt < 16; nt++) {
            #pragma unroll
            for (int m = 0; m < 2; m++) {
                const int col = 8 * nt + 2 * q + m;
                const float wt = __ldg(W0 + col);
                const float wx = __ldg(W0 + 128 + col);
                const float bb = __ldg(b0 + col);
                const float za = fmaf(wt, Pa.x, fmaf(wx, Pa.y, bb));
                const float zb = fmaf(wt, Pb.x, fmaf(wx, Pb.y, bb));
                const float a0 = tanhf_fast(za), a1 = tanhf_fast(zb);
                const float p0 = 1.0f - a0 * a0, p1 = 1.0f - a1 * a1;
                float va, vb;
                if (s == 0)      { va = a0;       vb = a1; }
                else if (s == 1) { va = p0 * wt;  vb = p1 * wt; }
                else if (s == 2) { va = p0 * wx;  vb = p1 * wx; }
                else             { va = -2.0f * a0 * p0 * wx * wx;
                                   vb = -2.0f * a1 * p1 * wx * wx; }
                c[nt][m] = va; c[nt][2 + m] = vb;
            }
        }

        // ---- 3 hidden GEMM layers ----
        #pragma unroll 1
        for (int l = 0; l < 3; l++) {
            uint32_t aH[8][4], aL[8][4];
            #pragma unroll
            for (int ks = 0; ks < 8; ks++) {
                split2(c[2*ks][0],   c[2*ks][1],   aH[ks][0], aL[ks][0]);
                split2(c[2*ks][2],   c[2*ks][3],   aH[ks][1], aL[ks][1]);
                split2(c[2*ks+1][0], c[2*ks+1][1], aH[ks][2], aL[ks][2]);
                split2(c[2*ks+1][2], c[2*ks+1][3], aH[ks][3], aL[ks][3]);
            }
            #pragma unroll
            for (int nt = 0; nt < 16; nt++) {
                c[nt][0] = 0.f; c[nt][1] = 0.f; c[nt][2] = 0.f; c[nt][3] = 0.f;
            }
            const uint2* bh = sWfH + l * 4096 + lane;
            const uint2* bl = sWfL + l * 4096 + lane;
            #pragma unroll
            for (int ks = 0; ks < 8; ks++) {
                const int base = ks * 16;
                #pragma unroll
                for (int nt = 0; nt < 16; nt++) {
                    const uint2 B = bh[(base + nt) * 32];
                    mma16816(c[nt], aH[ks], B.x, B.y);
                }
                #pragma unroll
                for (int nt = 0; nt < 16; nt++) {
                    const uint2 B = bh[(base + nt) * 32];
                    mma16816(c[nt], aL[ks], B.x, B.y);
                }
                #pragma unroll
                for (int nt = 0; nt < 16; nt++) {
                    const uint2 B = bl[(base + nt) * 32];
                    mma16816(c[nt], aH[ks], B.x, B.y);
                }
            }

            // ---- epilogue: tanh AD coupling via group-local smem exchange ----
            const float* bb = (l == 0) ? b1 : (l == 1) ? b2 : b3;
            if (s == 0) {
                #pragma unroll
                for (int nt = 0; nt < 16; nt++) {
                    const int col = 8 * nt + 2 * q;
                    const float bv0 = __ldg(bb + col);
                    const float bv1 = __ldg(bb + col + 1);
                    c[nt][0] = tanhf_fast(c[nt][0] + bv0);
                    c[nt][1] = tanhf_fast(c[nt][1] + bv1);
                    c[nt][2] = tanhf_fast(c[nt][2] + bv0);
                    c[nt][3] = tanhf_fast(c[nt][3] + bv1);
                    *(float2*)(exA + ra * 130 + col) = make_float2(c[nt][0], c[nt][1]);
                    *(float2*)(exA + rb * 130 + col) = make_float2(c[nt][2], c[nt][3]);
                }
            } else if (s == 2) {
                #pragma unroll
                for (int nt = 0; nt < 16; nt++) {
                    const int col = 8 * nt + 2 * q;
                    *(float2*)(exX + ra * 130 + col) = make_float2(c[nt][0], c[nt][1]);
                    *(float2*)(exX + rb * 130 + col) = make_float2(c[nt][2], c[nt][3]);
                }
            }
            gbar(bid);
            if (s != 0) {
                #pragma unroll
                for (int nt = 0; nt < 16; nt++) {
                    const int col = 8 * nt + 2 * q;
                    const float2 aA = *(const float2*)(exA + ra * 130 + col);
                    const float2 aB = *(const float2*)(exA + rb * 130 + col);
                    const float p0 = 1.0f - aA.x * aA.x, p1 = 1.0f - aA.y * aA.y;
                    const float p2 = 1.0f - aB.x * aB.x, p3 = 1.0f - aB.y * aB.y;
                    if (s == 3) {
                        const float2 xA = *(const float2*)(exX + ra * 130 + col);
                        const float2 xB = *(const float2*)(exX + rb * 130 + col);
                        c[nt][0] = p0 * fmaf(-2.0f * aA.x * xA.x, xA.x, c[nt][0]);
                        c[nt][1] = p1 * fmaf(-2.0f * aA.y * xA.y, xA.y, c[nt][1]);
                        c[nt][2] = p2 * fmaf(-2.0f * aB.x * xB.x, xB.x, c[nt][2]);
                        c[nt][3] = p3 * fmaf(-2.0f * aB.y * xB.y, xB.y, c[nt][3]);
                    } else {
                        c[nt][0] *= p0; c[nt][1] *= p1; c[nt][2] *= p2; c[nt][3] *= p3;
                    }
                }
            }
            gbar(bid);
        }

        // ---- layer 4: per-state dot with W4, quad reduce, combine ----
        {
            float d0 = 0.f, d1 = 0.f;
            #pragma unroll
            for (int nt = 0; nt < 16; nt++) {
                const int col = 8 * nt + 2 * q;
                const float w0v = __ldg(W4 + col), w1v = __ldg(W4 + col + 1);
                d0 = fmaf(w0v, c[nt][0], fmaf(w1v, c[nt][1], d0));
                d1 = fmaf(w0v, c[nt][2], fmaf(w1v, c[nt][3], d1));
            }
            d0 += __shfl_xor_sync(0xffffffffu, d0, 1);
            d0 += __shfl_xor_sync(0xffffffffu, d0, 2);
            d1 += __shfl_xor_sync(0xffffffffu, d1, 1);
            d1 += __shfl_xor_sync(0xffffffffu, d1, 2);
            if (q == 0) {
                exA[s * 16 + ra] = d0;
                exA[s * 16 + rb] = d1;
            }
            gbar(bid);
            if (s == 0 && lane < 16) {
                const int row = lane;
                const float u   = exA[row] + b4v;
                const float ut  = exA[16 + row];
                const float ux  = exA[32 + row];
                const float uxx = exA[48 + row];
                out[tile * 16 + row] =
                    (tile < TEQ) ? (fmaf(u, ux, ut) - NU * uxx) : u;
            }
            gbar(bid);
        }
    }
}

extern "C" void kernel_launch(void* const* d_in, const int* in_sizes, int n_in,
                              void* d_out, int out_size)
{
    const float* tx_eq   = (const float*)d_in[0];
    const float* tx_init = (const float*)d_in[1];
    const float* tx_bnd  = (const float*)d_in[2];
    const float* W0 = (const float*)d_in[3];
    const float* b0 = (const float*)d_in[4];
    const float* W1 = (const float*)d_in[5];
    const float* b1 = (const float*)d_in[6];
    const float* W2 = (const float*)d_in[7];
    const float* b2 = (const float*)d_in[8];
    const float* W3 = (const float*)d_in[9];
    const float* b3 = (const float*)d_in[10];
    const float* W4 = (const float*)d_in[11];
    const float* b4 = (const float*)d_in[12];
    float* out = (float*)d_out;

    prep_kernel<<<48, 256>>>(W1, W2, W3);

    cudaFuncSetAttribute(pinn_mma, cudaFuncAttributeMaxDynamicSharedMemorySize, SMEM_BYTES);
    int sms = 148;
    cudaDeviceGetAttribute(&sms, cudaDevAttrMultiProcessorCount, 0);

    pinn_mma<<<sms, 256, SMEM_BYTES>>>(tx_eq, tx_init, tx_bnd,
        W0, b0, b1, b2, b3, W4, b4, out);
}

// round 11
// speedup vs baseline: 1.0234x; 1.0234x over previous
#include <cuda_runtime.h>
#include <cuda_bf16.h>
#include <stdint.h>

#define NTILES 4352          // 139264 / 32 points
#define TEQ    4096
#define TIB    4224
#define NU     0.0031830988618379067154f

// W1..W3 bf16 fragments, h and l splits separate: [l][ks][nt][lane] -> uint2{b0,b1}
__device__ uint2 g_wfH[12288];
__device__ uint2 g_wfL[12288];

__device__ __forceinline__ uint32_t pkbf(float lo, float hi) {
    uint32_t r; asm("cvt.rn.bf16x2.f32 %0, %1, %2;" : "=r"(r) : "f"(hi), "f"(lo)); return r;
}
__device__ __forceinline__ void split2(float v0, float v1, uint32_t& h, uint32_t& l) {
    h = pkbf(v0, v1);
    float h0 = __uint_as_float(h << 16);
    float h1 = __uint_as_float(h & 0xffff0000u);
    l = pkbf(v0 - h0, v1 - h1);
}
__device__ __forceinline__ float tanhf_fast(float z) {
    float e = __expf(2.0f * z);
    return __fdividef(e - 1.0f, e + 1.0f);
}
__device__ __forceinline__ void mma16816(float* c, const uint32_t* a, uint32_t b0, uint32_t b1) {
    asm volatile(
        "mma.sync.aligned.m16n8k16.row.col.f32.bf16.bf16.f32 "
        "{%0,%1,%2,%3}, {%4,%5,%6,%7}, {%8,%9}, {%0,%1,%2,%3};"
        : "+f"(c[0]), "+f"(c[1]), "+f"(c[2]), "+f"(c[3])
        : "r"(a[0]), "r"(a[1]), "r"(a[2]), "r"(a[3]), "r"(b0), "r"(b1));
}

__global__ void prep_kernel(const float* __restrict__ W1,
                            const float* __restrict__ W2,
                            const float* __restrict__ W3)
{
    const int gt   = blockIdx.x * blockDim.x + threadIdx.x;   // 0..12287
    const int lane = gt & 31;
    const int wi   = gt >> 5;
    const int nt   = wi & 15;
    const int ks   = (wi >> 4) & 7;
    const int l    = wi >> 7;
    const float* W = (l == 0) ? W1 : (l == 1) ? W2 : W3;
    const int j  = nt * 8 + (lane >> 2);
    const int k0 = ks * 16 + 2 * (lane & 3);
    uint32_t h0, l0, h1, l1;
    split2(W[(k0    ) * 128 + j], W[(k0 + 1) * 128 + j], h0, l0);
    split2(W[(k0 + 8) * 128 + j], W[(k0 + 9) * 128 + j], h1, l1);
    g_wfH[wi * 32 + lane] = make_uint2(h0, h1);
    g_wfL[wi * 32 + lane] = make_uint2(l0, l1);
}

// smem: sWfH 98304 | sWfL 98304 | exA 16640 (stride 130) | exX 16640
#define EXA_OFF  196608
#define EXX_OFF  213248
#define SMEM_BYTES 229888

extern __shared__ char smem_raw[];

__global__ __launch_bounds__(256, 1)
void pinn_mma(const float* __restrict__ tx_eq, const float* __restrict__ tx_init,
              const float* __restrict__ tx_bnd,
              const float* __restrict__ W0, const float* __restrict__ b0,
              const float* __restrict__ b1, const float* __restrict__ b2,
              const float* __restrict__ b3,
              const float* __restrict__ W4, const float* __restrict__ b4,
              float* __restrict__ out)
{
    uint2* sWfH = (uint2*)smem_raw;
    uint2* sWfL = (uint2*)(smem_raw + 98304);
    float* exA  = (float*)(smem_raw + EXA_OFF);
    float* exX  = (float*)(smem_raw + EXX_OFF);

    const int tid  = threadIdx.x;
    const int lane = tid & 31;
    const int w    = tid >> 5;
    const int R    = w & 1;          // row-tile
    const int s    = w >> 1;         // state: 0=a 1=t 2=x 3=xx
    const int q    = lane & 3;
    const int ra   = 16 * R + (lane >> 2);
    const int rb   = ra + 8;

    {
        uint2* d = (uint2*)smem_raw;
        for (int i = tid; i < 12288; i += 256) { d[i] = g_wfH[i]; d[12288 + i] = g_wfL[i]; }
    }
    const float b4v = __ldg(b4);
    __syncthreads();

    for (int tile = blockIdx.x; tile < NTILES; tile += gridDim.x) {
        const float2* src;
        if (tile < TEQ)      src = (const float2*)tx_eq  + tile * 32;
        else if (tile < TIB) src = (const float2*)tx_init + (tile - TEQ) * 32;
        else                 src = (const float2*)tx_bnd  + (tile - TIB) * 32;

        const float2 Pa = __ldg(src + ra);
        const float2 Pb = __ldg(src + rb);

        float c[16][4];

        // ---- layer 0: every warp computes its state's seeds (C layout) ----
        #pragma unroll
        for (int nt = 0; nt < 16; nt++) {
            #pragma unroll
            for (int m = 0; m < 2; m++) {
                const int col = 8 * nt + 2 * q + m;
                const float wt = __ldg(W0 + col);
                const float wx = __ldg(W0 + 128 + col);
                const float bb = __ldg(b0 + col);
                const float za = fmaf(wt, Pa.x, fmaf(wx, Pa.y, bb));
                const float zb = fmaf(wt, Pb.x, fmaf(wx, Pb.y, bb));
                const float a0 = tanhf_fast(za), a1 = tanhf_fast(zb);
                const float p0 = 1.0f - a0 * a0, p1 = 1.0f - a1 * a1;
                float va, vb;
                if (s == 0)      { va = a0;       vb = a1; }
                else if (s == 1) { va = p0 * wt;  vb = p1 * wt; }
                else if (s == 2) { va = p0 * wx;  vb = p1 * wx; }
                else             { va = -2.0f * a0 * p0 * wx * wx;
                                   vb = -2.0f * a1 * p1 * wx * wx; }
                c[nt][m] = va; c[nt][2 + m] = vb;
            }
        }

        // ---- 3 hidden GEMM layers ----
        #pragma unroll 1
        for (int l = 0; l < 3; l++) {
            uint32_t aH[8][4], aL[8][4];
            #pragma unroll
            for (int ks = 0; ks < 8; ks++) {
                split2(c[2*ks][0],   c[2*ks][1],   aH[ks][0], aL[ks][0]);
                split2(c[2*ks][2],   c[2*ks][3],   aH[ks][1], aL[ks][1]);
                split2(c[2*ks+1][0], c[2*ks+1][1], aH[ks][2], aL[ks][2]);
                split2(c[2*ks+1][2], c[2*ks+1][3], aH[ks][3], aL[ks][3]);
            }
            #pragma unroll
            for (int nt = 0; nt < 16; nt++) {
                c[nt][0] = 0.f; c[nt][1] = 0.f; c[nt][2] = 0.f; c[nt][3] = 0.f;
            }
            const uint2* bh = sWfH + l * 4096 + lane;
            const uint2* bl = sWfL + l * 4096 + lane;
            #pragma unroll
            for (int ks = 0; ks < 8; ks++) {
                const uint2* ph = bh + ks * 512;   // 16 frags, stride 32
                const uint2* pl = bl + ks * 512;
                // one 48-MMA stream with a depth-4 register prefetch ring.
                // B stream: ph[0..15] (hh), ph[0..15] (lh), pl[0..15] (hl)
                uint2 rg[4];
                rg[0] = ph[0];   rg[1] = ph[32];
                rg[2] = ph[64];  rg[3] = ph[96];
                #pragma unroll
                for (int i = 0; i < 48; i++) {
                    const int nt = i & 15;
                    const uint32_t* a = (i < 16) ? aH[ks] : (i < 32) ? aL[ks] : aH[ks];
                    mma16816(c[nt], a, rg[i & 3].x, rg[i & 3].y);
                    const int j = i + 4;
                    if (j < 48) {
                        const uint2* sp = (j < 32) ? ph : pl;
                        rg[i & 3] = sp[(j & 15) * 32];
                    }
                }
            }

            // ---- epilogue: tanh AD coupling via smem exchange ----
            const float* bb = (l == 0) ? b1 : (l == 1) ? b2 : b3;
            if (s == 0) {
                #pragma unroll
                for (int nt = 0; nt < 16; nt++) {
                    const int col = 8 * nt + 2 * q;
                    const float bv0 = __ldg(bb + col);
                    const float bv1 = __ldg(bb + col + 1);
                    c[nt][0] = tanhf_fast(c[nt][0] + bv0);
                    c[nt][1] = tanhf_fast(c[nt][1] + bv1);
                    c[nt][2] = tanhf_fast(c[nt][2] + bv0);
                    c[nt][3] = tanhf_fast(c[nt][3] + bv1);
                    *(float2*)(exA + ra * 130 + col) = make_float2(c[nt][0], c[nt][1]);
                    *(float2*)(exA + rb * 130 + col) = make_float2(c[nt][2], c[nt][3]);
                }
            } else if (s == 2) {
                #pragma unroll
                for (int nt = 0; nt < 16; nt++) {
                    const int col = 8 * nt + 2 * q;
                    *(float2*)(exX + ra * 130 + col) = make_float2(c[nt][0], c[nt][1]);
                    *(float2*)(exX + rb * 130 + col) = make_float2(c[nt][2], c[nt][3]);
                }
            }
            __syncthreads();
            if (s != 0) {
                #pragma unroll
                for (int nt = 0; nt < 16; nt++) {
                    const int col = 8 * nt + 2 * q;
                    const float2 aA = *(const float2*)(exA + ra * 130 + col);
                    const float2 aB = *(const float2*)(exA + rb * 130 + col);
                    const float p0 = 1.0f - aA.x * aA.x, p1 = 1.0f - aA.y * aA.y;
                    const float p2 = 1.0f - aB.x * aB.x, p3 = 1.0f - aB.y * aB.y;
                    if (s == 3) {
                        const float2 xA = *(const float2*)(exX + ra * 130 + col);
                        const float2 xB = *(const float2*)(exX + rb * 130 + col);
                        c[nt][0] = p0 * fmaf(-2.0f * aA.x * xA.x, xA.x, c[nt][0]);
                        c[nt][1] = p1 * fmaf(-2.0f * aA.y * xA.y, xA.y, c[nt][1]);
                        c[nt][2] = p2 * fmaf(-2.0f * aB.x * xB.x, xB.x, c[nt][2]);
                        c[nt][3] = p3 * fmaf(-2.0f * aB.y * xB.y, xB.y, c[nt][3]);
                    } else {
                        c[nt][0] *= p0; c[nt][1] *= p1; c[nt][2] *= p2; c[nt][3] *= p3;
                    }
                }
            }
            __syncthreads();
        }

        // ---- layer 4: per-state dot with W4, quad reduce, combine ----
        {
            float d0 = 0.f, d1 = 0.f;
            #pragma unroll
            for (int nt = 0; nt < 16; nt++) {
                const int col = 8 * nt + 2 * q;
                const float w0v = __ldg(W4 + col), w1v = __ldg(W4 + col + 1);
                d0 = fmaf(w0v, c[nt][0], fmaf(w1v, c[nt][1], d0));
                d1 = fmaf(w0v, c[nt][2], fmaf(w1v, c[nt][3], d1));
            }
            d0 += __shfl_xor_sync(0xffffffffu, d0, 1);
            d0 += __shfl_xor_sync(0xffffffffu, d0, 2);
            d1 += __shfl_xor_sync(0xffffffffu, d1, 1);
            d1 += __shfl_xor_sync(0xffffffffu, d1, 2);
            if (q == 0) {
                exA[s * 32 + ra] = d0;
                exA[s * 32 + rb] = d1;
            }
            __syncthreads();
            if (w == 0) {
                const int row = lane;
                const float u   = exA[row] + b4v;
                const float ut  = exA[32 + row];
                const float ux  = exA[64 + row];
                const float uxx = exA[96 + row];
                out[tile * 32 + row] =
                    (tile < TEQ) ? (fmaf(u, ux, ut) - NU * uxx) : u;
            }
            __syncthreads();
        }
    }
}

extern "C" void kernel_launch(void* const* d_in, const int* in_sizes, int n_in,
                              void* d_out, int out_size)
{
    const float* tx_eq   = (const float*)d_in[0];
    const float* tx_init = (const float*)d_in[1];
    const float* tx_bnd  = (const float*)d_in[2];
    const float* W0 = (const float*)d_in[3];
    const float* b0 = (const float*)d_in[4];
    const float* W1 = (const float*)d_in[5];
    const float* b1 = (const float*)d_in[6];
    const float* W2 = (const float*)d_in[7];
    const float* b2 = (const float*)d_in[8];
    const float* W3 = (const float*)d_in[9];
    const float* b3 = (const float*)d_in[10];
    const float* W4 = (const float*)d_in[11];
    const float* b4 = (const float*)d_in[12];
    float* out = (float*)d_out;

    prep_kernel<<<48, 256>>>(W1, W2, W3);

    cudaFuncSetAttribute(pinn_mma, cudaFuncAttributeMaxDynamicSharedMemorySize, SMEM_BYTES);
    int sms = 148;
    cudaDeviceGetAttribute(&sms, cudaDevAttrMultiProcessorCount, 0);
    if (sms > NTILES) sms = NTILES;

    pinn_mma<<<sms, 256, SMEM_BYTES>>>(tx_eq, tx_init, tx_bnd,
        W0, b0, b1, b2, b3, W4, b4, out);
}

// round 12
// speedup vs baseline: 1.0561x; 1.0320x over previous
#include <cuda_runtime.h>
#include <cuda_bf16.h>
#include <stdint.h>

#define NTILES 4352          // 139264 / 32 points
#define TEQ    4096
#define TIB    4224
#define NU     0.0031830988618379067154f

// W1..W3 bf16 fragments, h and l splits: [l][ks][nt][lane] -> uint2{b0,b1}
__device__ uint2 g_wfH[12288];
__device__ uint2 g_wfL[12288];

__device__ __forceinline__ uint32_t pkbf(float lo, float hi) {
    uint32_t r; asm("cvt.rn.bf16x2.f32 %0, %1, %2;" : "=r"(r) : "f"(hi), "f"(lo)); return r;
}
__device__ __forceinline__ void split2(float v0, float v1, uint32_t& h, uint32_t& l) {
    h = pkbf(v0, v1);
    float h0 = __uint_as_float(h << 16);
    float h1 = __uint_as_float(h & 0xffff0000u);
    l = pkbf(v0 - h0, v1 - h1);
}
__device__ __forceinline__ float tanhf_fast(float z) {
    float e = __expf(2.0f * z);
    return __fdividef(e - 1.0f, e + 1.0f);
}
__device__ __forceinline__ void mma16816(float* c, const uint32_t* a, uint32_t b0, uint32_t b1) {
    asm volatile(
        "mma.sync.aligned.m16n8k16.row.col.f32.bf16.bf16.f32 "
        "{%0,%1,%2,%3}, {%4,%5,%6,%7}, {%8,%9}, {%0,%1,%2,%3};"
        : "+f"(c[0]), "+f"(c[1]), "+f"(c[2]), "+f"(c[3])
        : "r"(a[0]), "r"(a[1]), "r"(a[2]), "r"(a[3]), "r"(b0), "r"(b1));
}

__global__ void prep_kernel(const float* __restrict__ W1,
                            const float* __restrict__ W2,
                            const float* __restrict__ W3)
{
    const int gt   = blockIdx.x * blockDim.x + threadIdx.x;   // 0..12287
    const int lane = gt & 31;
    const int wi   = gt >> 5;
    const int nt   = wi & 15;
    const int ks   = (wi >> 4) & 7;
    const int l    = wi >> 7;
    const float* W = (l == 0) ? W1 : (l == 1) ? W2 : W3;
    const int j  = nt * 8 + (lane >> 2);
    const int k0 = ks * 16 + 2 * (lane & 3);
    uint32_t h0, l0, h1, l1;
    split2(W[(k0    ) * 128 + j], W[(k0 + 1) * 128 + j], h0, l0);
    split2(W[(k0 + 8) * 128 + j], W[(k0 + 9) * 128 + j], h1, l1);
    g_wfH[wi * 32 + lane] = make_uint2(h0, h1);
    g_wfL[wi * 32 + lane] = make_uint2(l0, l1);
}

// smem: whS 98304 | 5 state buffers of 32 x 132 floats (16896 B each)
#define ST_STRIDE 132
#define ST_FLOATS 4224
#define SMEM_BYTES (98304 + 5 * 16896)   // 182784

extern __shared__ char smem_raw[];

__global__ __launch_bounds__(512, 1)
void pinn_mma(const float* __restrict__ tx_eq, const float* __restrict__ tx_init,
              const float* __restrict__ tx_bnd,
              const float* __restrict__ W0, const float* __restrict__ b0,
              const float* __restrict__ b1, const float* __restrict__ b2,
              const float* __restrict__ b3,
              const float* __restrict__ W4, const float* __restrict__ b4,
              float* __restrict__ out)
{
    uint2* whS = (uint2*)smem_raw;
    float* stf = (float*)(smem_raw + 98304);
    float* st0 = stf;                  // a
    float* st1 = stf + ST_FLOATS;      // at
    float* st2 = stf + 2 * ST_FLOATS;  // raw zx (scratch within a layer)
    float* st3 = stf + 3 * ST_FLOATS;  // axx
    float* st4 = stf + 4 * ST_FLOATS;  // ax

    const int tid  = threadIdx.x;
    const int lane = tid & 31;
    const int wid  = tid >> 5;        // 0..15
    const int R    = wid & 1;         // row-half
    const int s    = (wid >> 1) & 3;  // state
    const int nh   = wid >> 3;        // N-half
    const int g    = lane >> 2;
    const int q    = lane & 3;
    const int ra   = 16 * R + g;
    const int rb   = ra + 8;

    // this warp's A-source buffer (its state's activation values)
    float* stS = (s == 0) ? st0 : (s == 1) ? st1 : (s == 2) ? st4 : st3;

    for (int i = tid; i < 12288; i += 512) whS[i] = g_wfH[i];
    const float b4v = __ldg(b4);
    __syncthreads();

    for (int tile = blockIdx.x; tile < NTILES; tile += gridDim.x) {
        const float2* src;
        if (tile < TEQ)      src = (const float2*)tx_eq  + tile * 32;
        else if (tile < TIB) src = (const float2*)tx_init + (tile - TEQ) * 32;
        else                 src = (const float2*)tx_bnd  + (tile - TIB) * 32;

        const float2 Pa = __ldg(src + ra);
        const float2 Pb = __ldg(src + rb);

        // ---- layer 0: each warp seeds its state for its rows/cols -> stS ----
        #pragma unroll
        for (int nt = 0; nt < 8; nt++) {
            float vA[2], vB[2];
            #pragma unroll
            for (int m = 0; m < 2; m++) {
                const int col = 64 * nh + 8 * nt + 2 * q + m;
                const float wt = __ldg(W0 + col);
                const float wx = __ldg(W0 + 128 + col);
                const float bb = __ldg(b0 + col);
                const float za = fmaf(wt, Pa.x, fmaf(wx, Pa.y, bb));
                const float zb = fmaf(wt, Pb.x, fmaf(wx, Pb.y, bb));
                const float a0 = tanhf_fast(za), a1 = tanhf_fast(zb);
                const float p0 = 1.0f - a0 * a0, p1 = 1.0f - a1 * a1;
                if (s == 0)      { vA[m] = a0;       vB[m] = a1; }
                else if (s == 1) { vA[m] = p0 * wt;  vB[m] = p1 * wt; }
                else if (s == 2) { vA[m] = p0 * wx;  vB[m] = p1 * wx; }
                else             { vA[m] = -2.0f * a0 * p0 * wx * wx;
                                   vB[m] = -2.0f * a1 * p1 * wx * wx; }
            }
            const int col0 = 64 * nh + 8 * nt + 2 * q;
            *(float2*)(stS + ra * ST_STRIDE + col0) = make_float2(vA[0], vA[1]);
            *(float2*)(stS + rb * ST_STRIDE + col0) = make_float2(vB[0], vB[1]);
        }
        __syncthreads();

        // ---- 3 hidden layers ----
        #pragma unroll 1
        for (int l = 0; l < 3; l++) {
            float c[8][4];
            #pragma unroll
            for (int nt = 0; nt < 8; nt++) {
                c[nt][0] = 0.f; c[nt][1] = 0.f; c[nt][2] = 0.f; c[nt][3] = 0.f;
            }
            const uint2* bh  = whS + l * 4096 + lane;
            const uint2* blg = g_wfL + l * 4096 + lane;

            #pragma unroll
            for (int ks = 0; ks < 8; ks++) {
                // prefetch W-low fragments from gmem (L1-hot after first tile)
                uint2 BL[8];
                #pragma unroll
                for (int nt = 0; nt < 8; nt++)
                    BL[nt] = __ldg(blg + (ks * 16 + 8 * nh + nt) * 32);
                // W-high fragments from smem
                uint2 BH[8];
                #pragma unroll
                for (int nt = 0; nt < 8; nt++)
                    BH[nt] = bh[(ks * 16 + 8 * nh + nt) * 32];
                // JIT A fragments (h + l split) from the state buffer
                const float2 v0 = *(const float2*)(stS + ra * ST_STRIDE + 16 * ks + 2 * q);
                const float2 v1 = *(const float2*)(stS + rb * ST_STRIDE + 16 * ks + 2 * q);
                const float2 v2 = *(const float2*)(stS + ra * ST_STRIDE + 16 * ks + 8 + 2 * q);
                const float2 v3 = *(const float2*)(stS + rb * ST_STRIDE + 16 * ks + 8 + 2 * q);
                uint32_t aH[4], aL[4];
                split2(v0.x, v0.y, aH[0], aL[0]);
                split2(v1.x, v1.y, aH[1], aL[1]);
                split2(v2.x, v2.y, aH[2], aL[2]);
                split2(v3.x, v3.y, aH[3], aL[3]);
                #pragma unroll
                for (int nt = 0; nt < 8; nt++) mma16816(c[nt], aH, BH[nt].x, BH[nt].y);
                #pragma unroll
                for (int nt = 0; nt < 8; nt++) mma16816(c[nt], aL, BH[nt].x, BH[nt].y);
                #pragma unroll
                for (int nt = 0; nt < 8; nt++) mma16816(c[nt], aH, BL[nt].x, BL[nt].y);
            }
            __syncthreads();   // all A-reads of stS complete before rewrites

            const float* bb = (l == 0) ? b1 : (l == 1) ? b2 : b3;
            // phase A: s0 activates + publishes a; s2 publishes raw zx
            if (s == 0) {
                #pragma unroll
                for (int nt = 0; nt < 8; nt++) {
                    const int col0 = 64 * nh + 8 * nt + 2 * q;
                    const float bv0 = __ldg(bb + col0);
                    const float bv1 = __ldg(bb + col0 + 1);
                    const float a00 = tanhf_fast(c[nt][0] + bv0);
                    const float a01 = tanhf_fast(c[nt][1] + bv1);
                    const float a10 = tanhf_fast(c[nt][2] + bv0);
                    const float a11 = tanhf_fast(c[nt][3] + bv1);
                    *(float2*)(st0 + ra * ST_STRIDE + col0) = make_float2(a00, a01);
                    *(float2*)(st0 + rb * ST_STRIDE + col0) = make_float2(a10, a11);
                }
            } else if (s == 2) {
                #pragma unroll
                for (int nt = 0; nt < 8; nt++) {
                    const int col0 = 64 * nh + 8 * nt + 2 * q;
                    *(float2*)(st2 + ra * ST_STRIDE + col0) = make_float2(c[nt][0], c[nt][1]);
                    *(float2*)(st2 + rb * ST_STRIDE + col0) = make_float2(c[nt][2], c[nt][3]);
                }
            }
            __syncthreads();
            // phase B: derivative states apply tanh coupling
            if (s != 0) {
                #pragma unroll
                for (int nt = 0; nt < 8; nt++) {
                    const int col0 = 64 * nh + 8 * nt + 2 * q;
                    const float2 aA = *(const float2*)(st0 + ra * ST_STRIDE + col0);
                    const float2 aB = *(const float2*)(st0 + rb * ST_STRIDE + col0);
                    const float p00 = 1.0f - aA.x * aA.x, p01 = 1.0f - aA.y * aA.y;
                    const float p10 = 1.0f - aB.x * aB.x, p11 = 1.0f - aB.y * aB.y;
                    float o0, o1, o2, o3;
                    if (s == 3) {
                        const float2 xA = *(const float2*)(st2 + ra * ST_STRIDE + col0);
                        const float2 xB = *(const float2*)(st2 + rb * ST_STRIDE + col0);
                        o0 = p00 * fmaf(-2.0f * aA.x * xA.x, xA.x, c[nt][0]);
                        o1 = p01 * fmaf(-2.0f * aA.y * xA.y, xA.y, c[nt][1]);
                        o2 = p10 * fmaf(-2.0f * aB.x * xB.x, xB.x, c[nt][2]);
                        o3 = p11 * fmaf(-2.0f * aB.y * xB.y, xB.y, c[nt][3]);
                    } else {
                        o0 = p00 * c[nt][0]; o1 = p01 * c[nt][1];
                        o2 = p10 * c[nt][2]; o3 = p11 * c[nt][3];
                    }
                    float* dst = (s == 1) ? st1 : (s == 2) ? st4 : st3;
                    *(float2*)(dst + ra * ST_STRIDE + col0) = make_float2(o0, o1);
                    *(float2*)(dst + rb * ST_STRIDE + col0) = make_float2(o2, o3);
                }
            }
            __syncthreads();
        }

        // ---- layer 4: warp wid reduces rows 2wid, 2wid+1 over all states ----
        {
            float acc[2][4];
            #pragma unroll
            for (int r = 0; r < 2; r++)
                #pragma unroll
                for (int k = 0; k < 4; k++) acc[r][k] = 0.f;
            #pragma unroll
            for (int m = 0; m < 4; m++) {
                const int j = lane + 32 * m;
                const float w4 = __ldg(W4 + j);
                #pragma unroll
                for (int r = 0; r < 2; r++) {
                    const int row = 2 * wid + r;
                    acc[r][0] = fmaf(w4, st0[row * ST_STRIDE + j], acc[r][0]);
                    acc[r][1] = fmaf(w4, st1[row * ST_STRIDE + j], acc[r][1]);
                    acc[r][2] = fmaf(w4, st4[row * ST_STRIDE + j], acc[r][2]);
                    acc[r][3] = fmaf(w4, st3[row * ST_STRIDE + j], acc[r][3]);
                }
            }
            #pragma unroll
            for (int off = 16; off > 0; off >>= 1)
                #pragma unroll
                for (int r = 0; r < 2; r++)
                    #pragma unroll
                    for (int k = 0; k < 4; k++)
                        acc[r][k] += __shfl_down_sync(0xffffffffu, acc[r][k], off);
            if (lane == 0) {
                #pragma unroll
                for (int r = 0; r < 2; r++) {
                    const float u   = acc[r][0] + b4v;
                    const float ut  = acc[r][1];
                    const float ux  = acc[r][2];
                    const float uxx = acc[r][3];
                    out[tile * 32 + 2 * wid + r] =
                        (tile < TEQ) ? (fmaf(u, ux, ut) - NU * uxx) : u;
                }
            }
        }
        __syncthreads();
    }
}

extern "C" void kernel_launch(void* const* d_in, const int* in_sizes, int n_in,
                              void* d_out, int out_size)
{
    const float* tx_eq   = (const float*)d_in[0];
    const float* tx_init = (const float*)d_in[1];
    const float* tx_bnd  = (const float*)d_in[2];
    const float* W0 = (const float*)d_in[3];
    const float* b0 = (const float*)d_in[4];
    const float* W1 = (const float*)d_in[5];
    const float* b1 = (const float*)d_in[6];
    const float* W2 = (const float*)d_in[7];
    const float* b2 = (const float*)d_in[8];
    const float* W3 = (const float*)d_in[9];
    const float* b3 = (const float*)d_in[10];
    const float* W4 = (const float*)d_in[11];
    const float* b4 = (const float*)d_in[12];
    float* out = (float*)d_out;

    prep_kernel<<<48, 256>>>(W1, W2, W3);

    cudaFuncSetAttribute(pinn_mma, cudaFuncAttributeMaxDynamicSharedMemorySize, SMEM_BYTES);
    int sms = 148;
    cudaDeviceGetAttribute(&sms, cudaDevAttrMultiProcessorCount, 0);
    if (sms > NTILES) sms = NTILES;

    pinn_mma<<<sms, 512, SMEM_BYTES>>>(tx_eq, tx_init, tx_bnd,
        W0, b0, b1, b2, b3, W4, b4, out);
}

// round 13
// speedup vs baseline: 1.0585x; 1.0022x over previous
#include <cuda_runtime.h>
#include <cuda_bf16.h>
#include <stdint.h>

#define NTILES 4352          // 139264 / 32 points
#define TEQ    4096
#define TIB    4224
#define NU     0.0031830988618379067154f

// W1..W3 bf16 fragments, h and l splits: [l][ks][nt][lane] -> uint2{b0,b1}
__device__ uint2 g_wfH[12288];
__device__ uint2 g_wfL[12288];

__device__ __forceinline__ uint32_t pkbf(float lo, float hi) {
    uint32_t r; asm("cvt.rn.bf16x2.f32 %0, %1, %2;" : "=r"(r) : "f"(hi), "f"(lo)); return r;
}
__device__ __forceinline__ void split2(float v0, float v1, uint32_t& h, uint32_t& l) {
    h = pkbf(v0, v1);
    float h0 = __uint_as_float(h << 16);
    float h1 = __uint_as_float(h & 0xffff0000u);
    l = pkbf(v0 - h0, v1 - h1);
}
__device__ __forceinline__ float tanhf_fast(float z) {
    float e = __expf(2.0f * z);
    return __fdividef(e - 1.0f, e + 1.0f);
}
__device__ __forceinline__ void mma16816(float* c, const uint32_t* a, uint32_t b0, uint32_t b1) {
    asm volatile(
        "mma.sync.aligned.m16n8k16.row.col.f32.bf16.bf16.f32 "
        "{%0,%1,%2,%3}, {%4,%5,%6,%7}, {%8,%9}, {%0,%1,%2,%3};"
        : "+f"(c[0]), "+f"(c[1]), "+f"(c[2]), "+f"(c[3])
        : "r"(a[0]), "r"(a[1]), "r"(a[2]), "r"(a[3]), "r"(b0), "r"(b1));
}

__global__ void prep_kernel(const float* __restrict__ W1,
                            const float* __restrict__ W2,
                            const float* __restrict__ W3)
{
    const int gt   = blockIdx.x * blockDim.x + threadIdx.x;   // 0..12287
    const int lane = gt & 31;
    const int wi   = gt >> 5;
    const int nt   = wi & 15;
    const int ks   = (wi >> 4) & 7;
    const int l    = wi >> 7;
    const float* W = (l == 0) ? W1 : (l == 1) ? W2 : W3;
    const int j  = nt * 8 + (lane >> 2);
    const int k0 = ks * 16 + 2 * (lane & 3);
    uint32_t h0, l0, h1, l1;
    split2(W[(k0    ) * 128 + j], W[(k0 + 1) * 128 + j], h0, l0);
    split2(W[(k0 + 8) * 128 + j], W[(k0 + 9) * 128 + j], h1, l1);
    g_wfH[wi * 32 + lane] = make_uint2(h0, h1);
    g_wfL[wi * 32 + lane] = make_uint2(l0, l1);
}

// smem: whS 98304 | 5 state buffers of 32 x 132 floats (16896 B each)
#define ST_STRIDE 132
#define ST_FLOATS 4224
#define SMEM_BYTES (98304 + 5 * 16896)   // 182784

extern __shared__ char smem_raw[];

__global__ __launch_bounds__(512, 1)
void pinn_mma(const float* __restrict__ tx_eq, const float* __restrict__ tx_init,
              const float* __restrict__ tx_bnd,
              const float* __restrict__ W0, const float* __restrict__ b0,
              const float* __restrict__ b1, const float* __restrict__ b2,
              const float* __restrict__ b3,
              const float* __restrict__ W4, const float* __restrict__ b4,
              float* __restrict__ out)
{
    uint2* whS = (uint2*)smem_raw;
    float* stf = (float*)(smem_raw + 98304);
    float* st0 = stf;                  // a
    float* st1 = stf + ST_FLOATS;      // at
    float* st2 = stf + 2 * ST_FLOATS;  // raw zx (scratch within a layer)
    float* st3 = stf + 3 * ST_FLOATS;  // axx
    float* st4 = stf + 4 * ST_FLOATS;  // ax

    const int tid  = threadIdx.x;
    const int lane = tid & 31;
    const int wid  = tid >> 5;        // 0..15
    const int R    = wid & 1;         // row-half
    const int s    = (wid >> 1) & 3;  // state
    const int nh   = wid >> 3;        // N-half
    const int g    = lane >> 2;
    const int q    = lane & 3;
    const int ra   = 16 * R + g;
    const int rb   = ra + 8;

    // this warp's A-source buffer (its state's activation values)
    float* stS = (s == 0) ? st0 : (s == 1) ? st1 : (s == 2) ? st4 : st3;

    for (int i = tid; i < 12288; i += 512) whS[i] = g_wfH[i];
    const float b4v = __ldg(b4);
    __syncthreads();

    for (int tile = blockIdx.x; tile < NTILES; tile += gridDim.x) {
        const float2* src;
        if (tile < TEQ)      src = (const float2*)tx_eq  + tile * 32;
        else if (tile < TIB) src = (const float2*)tx_init + (tile - TEQ) * 32;
        else                 src = (const float2*)tx_bnd  + (tile - TIB) * 32;

        const float2 Pa = __ldg(src + ra);
        const float2 Pb = __ldg(src + rb);

        // ---- layer 0: each warp seeds its state for its rows/cols -> stS ----
        #pragma unroll
        for (int nt = 0; nt < 8; nt++) {
            float vA[2], vB[2];
            #pragma unroll
            for (int m = 0; m < 2; m++) {
                const int col = 64 * nh + 8 * nt + 2 * q + m;
                const float wt = __ldg(W0 + col);
                const float wx = __ldg(W0 + 128 + col);
                const float bb = __ldg(b0 + col);
                const float za = fmaf(wt, Pa.x, fmaf(wx, Pa.y, bb));
                const float zb = fmaf(wt, Pb.x, fmaf(wx, Pb.y, bb));
                const float a0 = tanhf_fast(za), a1 = tanhf_fast(zb);
                const float p0 = 1.0f - a0 * a0, p1 = 1.0f - a1 * a1;
                if (s == 0)      { vA[m] = a0;       vB[m] = a1; }
                else if (s == 1) { vA[m] = p0 * wt;  vB[m] = p1 * wt; }
                else if (s == 2) { vA[m] = p0 * wx;  vB[m] = p1 * wx; }
                else             { vA[m] = -2.0f * a0 * p0 * wx * wx;
                                   vB[m] = -2.0f * a1 * p1 * wx * wx; }
            }
            const int col0 = 64 * nh + 8 * nt + 2 * q;
            *(float2*)(stS + ra * ST_STRIDE + col0) = make_float2(vA[0], vA[1]);
            *(float2*)(stS + rb * ST_STRIDE + col0) = make_float2(vB[0], vB[1]);
        }
        __syncthreads();

        // ---- 3 hidden layers ----
        #pragma unroll 1
        for (int l = 0; l < 3; l++) {
            float c[8][4];
            #pragma unroll
            for (int nt = 0; nt < 8; nt++) {
                c[nt][0] = 0.f; c[nt][1] = 0.f; c[nt][2] = 0.f; c[nt][3] = 0.f;
            }
            const uint2* bh  = whS + l * 4096 + lane;
            const uint2* blg = g_wfL + l * 4096 + lane;

            #pragma unroll
            for (int ks = 0; ks < 8; ks++) {
                // prefetch W-low fragments from gmem (L1-hot after first tile)
                uint2 BL[8];
                #pragma unroll
                for (int nt = 0; nt < 8; nt++)
                    BL[nt] = __ldg(blg + (ks * 16 + 8 * nh + nt) * 32);
                // W-high fragments from smem
                uint2 BH[8];
                #pragma unroll
                for (int nt = 0; nt < 8; nt++)
                    BH[nt] = bh[(ks * 16 + 8 * nh + nt) * 32];
                // JIT A fragments (h + l split) from the state buffer
                const float2 v0 = *(const float2*)(stS + ra * ST_STRIDE + 16 * ks + 2 * q);
                const float2 v1 = *(const float2*)(stS + rb * ST_STRIDE + 16 * ks + 2 * q);
                const float2 v2 = *(const float2*)(stS + ra * ST_STRIDE + 16 * ks + 8 + 2 * q);
                const float2 v3 = *(const float2*)(stS + rb * ST_STRIDE + 16 * ks + 8 + 2 * q);
                uint32_t aH[4], aL[4];
                split2(v0.x, v0.y, aH[0], aL[0]);
                split2(v1.x, v1.y, aH[1], aL[1]);
                split2(v2.x, v2.y, aH[2], aL[2]);
                split2(v3.x, v3.y, aH[3], aL[3]);
                #pragma unroll
                for (int nt = 0; nt < 8; nt++) mma16816(c[nt], aH, BH[nt].x, BH[nt].y);
                #pragma unroll
                for (int nt = 0; nt < 8; nt++) mma16816(c[nt], aL, BH[nt].x, BH[nt].y);
                #pragma unroll
                for (int nt = 0; nt < 8; nt++) mma16816(c[nt], aH, BL[nt].x, BL[nt].y);
            }
            __syncthreads();   // all A-reads of stS complete before rewrites

            const float* bb = (l == 0) ? b1 : (l == 1) ? b2 : b3;
            // phase A: s0 activates + publishes a; s2 publishes raw zx
            if (s == 0) {
                #pragma unroll
                for (int nt = 0; nt < 8; nt++) {
                    const int col0 = 64 * nh + 8 * nt + 2 * q;
                    const float bv0 = __ldg(bb + col0);
                    const float bv1 = __ldg(bb + col0 + 1);
                    const float a00 = tanhf_fast(c[nt][0] + bv0);
                    const float a01 = tanhf_fast(c[nt][1] + bv1);
                    const float a10 = tanhf_fast(c[nt][2] + bv0);
                    const float a11 = tanhf_fast(c[nt][3] + bv1);
                    *(float2*)(st0 + ra * ST_STRIDE + col0) = make_float2(a00, a01);
                    *(float2*)(st0 + rb * ST_STRIDE + col0) = make_float2(a10, a11);
                }
            } else if (s == 2) {
                #pragma unroll
                for (int nt = 0; nt < 8; nt++) {
                    const int col0 = 64 * nh + 8 * nt + 2 * q;
                    *(float2*)(st2 + ra * ST_STRIDE + col0) = make_float2(c[nt][0], c[nt][1]);
                    *(float2*)(st2 + rb * ST_STRIDE + col0) = make_float2(c[nt][2], c[nt][3]);
                }
            }
            __syncthreads();
            // phase B: derivative states apply tanh coupling
            if (s != 0) {
                #pragma unroll
                for (int nt = 0; nt < 8; nt++) {
                    const int col0 = 64 * nh + 8 * nt + 2 * q;
                    const float2 aA = *(const float2*)(st0 + ra * ST_STRIDE + col0);
                    const float2 aB = *(const float2*)(st0 + rb * ST_STRIDE + col0);
                    const float p00 = 1.0f - aA.x * aA.x, p01 = 1.0f - aA.y * aA.y;
                    const float p10 = 1.0f - aB.x * aB.x, p11 = 1.0f - aB.y * aB.y;
                    float o0, o1, o2, o3;
                    if (s == 3) {
                        const float2 xA = *(const float2*)(st2 + ra * ST_STRIDE + col0);
                        const float2 xB = *(const float2*)(st2 + rb * ST_STRIDE + col0);
                        o0 = p00 * fmaf(-2.0f * aA.x * xA.x, xA.x, c[nt][0]);
                        o1 = p01 * fmaf(-2.0f * aA.y * xA.y, xA.y, c[nt][1]);
                        o2 = p10 * fmaf(-2.0f * aB.x * xB.x, xB.x, c[nt][2]);
                        o3 = p11 * fmaf(-2.0f * aB.y * xB.y, xB.y, c[nt][3]);
                    } else {
                        o0 = p00 * c[nt][0]; o1 = p01 * c[nt][1];
                        o2 = p10 * c[nt][2]; o3 = p11 * c[nt][3];
                    }
                    float* dst = (s == 1) ? st1 : (s == 2) ? st4 : st3;
                    *(float2*)(dst + ra * ST_STRIDE + col0) = make_float2(o0, o1);
                    *(float2*)(dst + rb * ST_STRIDE + col0) = make_float2(o2, o3);
                }
            }
            __syncthreads();
        }

        // ---- layer 4: warp wid reduces rows 2wid, 2wid+1 over all states ----
        {
            float acc[2][4];
            #pragma unroll
            for (int r = 0; r < 2; r++)
                #pragma unroll
                for (int k = 0; k < 4; k++) acc[r][k] = 0.f;
            #pragma unroll
            for (int m = 0; m < 4; m++) {
                const int j = lane + 32 * m;
                const float w4 = __ldg(W4 + j);
                #pragma unroll
                for (int r = 0; r < 2; r++) {
                    const int row = 2 * wid + r;
                    acc[r][0] = fmaf(w4, st0[row * ST_STRIDE + j], acc[r][0]);
                    acc[r][1] = fmaf(w4, st1[row * ST_STRIDE + j], acc[r][1]);
                    acc[r][2] = fmaf(w4, st4[row * ST_STRIDE + j], acc[r][2]);
                    acc[r][3] = fmaf(w4, st3[row * ST_STRIDE + j], acc[r][3]);
                }
            }
            #pragma unroll
            for (int off = 16; off > 0; off >>= 1)
                #pragma unroll
                for (int r = 0; r < 2; r++)
                    #pragma unroll
                    for (int k = 0; k < 4; k++)
                        acc[r][k] += __shfl_down_sync(0xffffffffu, acc[r][k], off);
            if (lane == 0) {
                #pragma unroll
                for (int r = 0; r < 2; r++) {
                    const float u   = acc[r][0] + b4v;
                    const float ut  = acc[r][1];
                    const float ux  = acc[r][2];
                    const float uxx = acc[r][3];
                    out[tile * 32 + 2 * wid + r] =
                        (tile < TEQ) ? (fmaf(u, ux, ut) - NU * uxx) : u;
                }
            }
        }
        __syncthreads();
    }
}

extern "C" void kernel_launch(void* const* d_in, const int* in_sizes, int n_in,
                              void* d_out, int out_size)
{
    const float* tx_eq   = (const float*)d_in[0];
    const float* tx_init = (const float*)d_in[1];
    const float* tx_bnd  = (const float*)d_in[2];
    const float* W0 = (const float*)d_in[3];
    const float* b0 = (const float*)d_in[4];
    const float* W1 = (const float*)d_in[5];
    const float* b1 = (const float*)d_in[6];
    const float* W2 = (const float*)d_in[7];
    const float* b2 = (const float*)d_in[8];
    const float* W3 = (const float*)d_in[9];
    const float* b3 = (const float*)d_in[10];
    const float* W4 = (const float*)d_in[11];
    const float* b4 = (const float*)d_in[12];
    float* out = (float*)d_out;

    prep_kernel<<<48, 256>>>(W1, W2, W3);

    cudaFuncSetAttribute(pinn_mma, cudaFuncAttributeMaxDynamicSharedMemorySize, SMEM_BYTES);
    int sms = 148;
    cudaDeviceGetAttribute(&sms, cudaDevAttrMultiProcessorCount, 0);
    if (sms > NTILES) sms = NTILES;

    pinn_mma<<<sms, 512, SMEM_BYTES>>>(tx_eq, tx_init, tx_bnd,
        W0, b0, b1, b2, b3, W4, b4, out);
}